// round 1
// baseline (speedup 1.0000x reference)
#include <cuda_runtime.h>
#include <math.h>

#define BB 2
#define LSEQ 1024
#define DM 256
#define DI 512
#define DS 64
#define NH 8
#define HD 64
#define CD 640
#define DIP 1160
#define M2 (BB*LSEQ)
#define NLAYERS 2

// ---- scratch layout (floats) ----
// h (2 dirs)      : 2*M2*DM
// zxbcdt (2 dirs) : 2*M2*DIP
// conv out (2)    : 2*M2*CD
// dt (2)          : 2*M2*NH
// y (2)           : 2*M2*DI
// normed (2)      : 2*M2*DI
// comb            : M2*2*DM
// gate logits     : M2*2*DM
static constexpr size_t OFF_H    = 0;
static constexpr size_t OFF_ZX   = OFF_H    + (size_t)2*M2*DM;
static constexpr size_t OFF_CONV = OFF_ZX   + (size_t)2*M2*DIP;
static constexpr size_t OFF_DT   = OFF_CONV + (size_t)2*M2*CD;
static constexpr size_t OFF_Y    = OFF_DT   + (size_t)2*M2*NH;
static constexpr size_t OFF_NRM  = OFF_Y    + (size_t)2*M2*DI;
static constexpr size_t OFF_COMB = OFF_NRM  + (size_t)2*M2*DI;
static constexpr size_t OFF_GATE = OFF_COMB + (size_t)M2*2*DM;
static constexpr size_t SCRATCH_TOTAL = OFF_GATE + (size_t)M2*2*DM;

__device__ float g_scratch[SCRATCH_TOTAL];

// ---------------- embedding (writes fwd h and time-flipped bwd h) -------------
__global__ void k_embed(const int* __restrict__ ids, const float* __restrict__ mask,
                        const float* __restrict__ tok, const float* __restrict__ pos) {
    int bl = blockIdx.x;          // b*LSEQ + l
    int d  = threadIdx.x;         // 0..255
    int b = bl / LSEQ, l = bl % LSEQ;
    int id = ids[bl];
    float v = (tok[(size_t)id*DM + d] + pos[(size_t)l*DM + d]) * mask[bl];
    g_scratch[OFF_H + (size_t)bl*DM + d] = v;
    g_scratch[OFF_H + (size_t)M2*DM + ((size_t)b*LSEQ + (LSEQ-1-l))*DM + d] = v;
}

// ---------------- generic C[M,N] = A[M,K] * W[N,K]^T ------------------------
// 64x64 tile, 256 threads, 4x4 microtile, BK=16. K must be mult of 16, M mult of 64.
__global__ __launch_bounds__(256) void k_gemm_nt(
        const float* __restrict__ A, const float* __restrict__ W,
        float* __restrict__ C, int M, int N, int K) {
    __shared__ float As[16][64];
    __shared__ float Ws[16][64];
    int tid = threadIdx.x;
    int m0 = blockIdx.y * 64, n0 = blockIdx.x * 64;
    int row = tid >> 2, kq = tid & 3;   // load mapping
    int ty = tid >> 4, tx = tid & 15;   // compute mapping
    float c[4][4];
#pragma unroll
    for (int i = 0; i < 4; i++)
#pragma unroll
        for (int j = 0; j < 4; j++) c[i][j] = 0.f;

    for (int k0 = 0; k0 < K; k0 += 16) {
        float4 av = *(const float4*)(A + (size_t)(m0+row)*K + k0 + kq*4);
        float4 wv = make_float4(0.f, 0.f, 0.f, 0.f);
        if (n0 + row < N)
            wv = *(const float4*)(W + (size_t)(n0+row)*K + k0 + kq*4);
        __syncthreads();
        As[kq*4+0][row] = av.x; As[kq*4+1][row] = av.y;
        As[kq*4+2][row] = av.z; As[kq*4+3][row] = av.w;
        Ws[kq*4+0][row] = wv.x; Ws[kq*4+1][row] = wv.y;
        Ws[kq*4+2][row] = wv.z; Ws[kq*4+3][row] = wv.w;
        __syncthreads();
#pragma unroll
        for (int kk = 0; kk < 16; kk++) {
            float4 a = *(const float4*)(&As[kk][ty*4]);
            float4 w = *(const float4*)(&Ws[kk][tx*4]);
            c[0][0] += a.x*w.x; c[0][1] += a.x*w.y; c[0][2] += a.x*w.z; c[0][3] += a.x*w.w;
            c[1][0] += a.y*w.x; c[1][1] += a.y*w.y; c[1][2] += a.y*w.z; c[1][3] += a.y*w.w;
            c[2][0] += a.z*w.x; c[2][1] += a.z*w.y; c[2][2] += a.z*w.z; c[2][3] += a.z*w.w;
            c[3][0] += a.w*w.x; c[3][1] += a.w*w.y; c[3][2] += a.w*w.z; c[3][3] += a.w*w.w;
        }
    }
#pragma unroll
    for (int i = 0; i < 4; i++) {
        int m = m0 + ty*4 + i;
#pragma unroll
        for (int j = 0; j < 4; j++) {
            int n = n0 + tx*4 + j;
            if (n < N) C[(size_t)m*N + n] = c[i][j];
        }
    }
}

// ---------------- depthwise causal conv(4) + SiLU + dt softplus -------------
__global__ void k_conv(const float* __restrict__ cw, const float* __restrict__ cbias,
                       const float* __restrict__ dtb, int layer) {
    int dir = blockIdx.y;
    int bl = blockIdx.x;
    int b = bl / LSEQ, l = bl % LSEQ;
    int c = threadIdx.x;              // 0..639
    int li = dir*NLAYERS + layer;
    const float* zx = g_scratch + OFF_ZX + (size_t)dir*M2*DIP;
    float4 w = *(const float4*)(cw + ((size_t)li*CD + c)*4);
    float wk[4] = {w.x, w.y, w.z, w.w};
    float acc = 0.f;
#pragma unroll
    for (int k = 0; k < 4; k++) {
        int ls = l - 3 + k;
        if (ls >= 0)
            acc += zx[((size_t)b*LSEQ + ls)*DIP + DI + c] * wk[k];
    }
    acc += cbias[(size_t)li*CD + c];
    float s = acc / (1.f + __expf(-acc));
    g_scratch[OFF_CONV + (size_t)dir*M2*CD + (size_t)bl*CD + c] = s;
    if (c < NH) {
        float raw = zx[(size_t)bl*DIP + DI + CD + c] + dtb[li*NH + c];
        float sp = (raw > 20.f) ? raw : log1pf(expf(raw));
        g_scratch[OFF_DT + (size_t)dir*M2*NH + (size_t)bl*NH + c] = sp;
    }
}

// ---------------- SSM scan -------------------------------------------------
// grid: dir(2) x b(2) x head(8) x pgroup(4 of 16 rows) = 128 blocks, 128 thr
// thread: pl = t>>3 (local p row), ql = t&7 (8 states each). No barriers.
__global__ __launch_bounds__(128) void k_scan(const float* __restrict__ A_log,
                                              const float* __restrict__ Dp, int layer) {
    int blk = blockIdx.x;
    int pg = blk & 3; blk >>= 2;
    int hh = blk & 7; blk >>= 3;
    int b  = blk & 1; int dir = blk >> 1;
    int t = threadIdx.x;
    int ql = t & 7, pl = t >> 3;
    int p = pg*16 + pl;
    int n0 = ql*8;
    int li = dir*NLAYERS + layer;
    float Aa = -expf(A_log[li*NH + hh]);
    float Dv = Dp[li*NH + hh];
    const float* conv = g_scratch + OFF_CONV + (size_t)dir*M2*CD + (size_t)b*LSEQ*CD;
    const float* dt   = g_scratch + OFF_DT   + (size_t)dir*M2*NH + (size_t)b*LSEQ*NH;
    float* y          = g_scratch + OFF_Y    + (size_t)dir*M2*DI + (size_t)b*LSEQ*DI;

    float h[8];
#pragma unroll
    for (int j = 0; j < 8; j++) h[j] = 0.f;

    // prefetch step 0
    float4 B0 = *(const float4*)(conv + DI + n0);
    float4 B1 = *(const float4*)(conv + DI + n0 + 4);
    float4 C0 = *(const float4*)(conv + DI + DS + n0);
    float4 C1 = *(const float4*)(conv + DI + DS + n0 + 4);
    float xv  = conv[hh*HD + p];
    float dtv = dt[hh];

    for (int s = 0; s < LSEQ; s++) {
        int sp = (s + 1 < LSEQ) ? (s + 1) : (LSEQ - 1);
        const float* cr = conv + (size_t)sp*CD;
        float4 nB0 = *(const float4*)(cr + DI + n0);
        float4 nB1 = *(const float4*)(cr + DI + n0 + 4);
        float4 nC0 = *(const float4*)(cr + DI + DS + n0);
        float4 nC1 = *(const float4*)(cr + DI + DS + n0 + 4);
        float nx   = cr[hh*HD + p];
        float ndt  = dt[(size_t)sp*NH + hh];

        float dA = __expf(dtv * Aa);
        float sc = dtv * xv;
        float acc;
        h[0] = h[0]*dA + sc*B0.x; acc  = h[0]*C0.x;
        h[1] = h[1]*dA + sc*B0.y; acc += h[1]*C0.y;
        h[2] = h[2]*dA + sc*B0.z; acc += h[2]*C0.z;
        h[3] = h[3]*dA + sc*B0.w; acc += h[3]*C0.w;
        h[4] = h[4]*dA + sc*B1.x; acc += h[4]*C1.x;
        h[5] = h[5]*dA + sc*B1.y; acc += h[5]*C1.y;
        h[6] = h[6]*dA + sc*B1.z; acc += h[6]*C1.z;
        h[7] = h[7]*dA + sc*B1.w; acc += h[7]*C1.w;

        acc += __shfl_xor_sync(0xffffffffu, acc, 1);
        acc += __shfl_xor_sync(0xffffffffu, acc, 2);
        acc += __shfl_xor_sync(0xffffffffu, acc, 4);
        if (ql == 0) y[(size_t)s*DI + hh*HD + p] = acc + Dv*xv;

        B0 = nB0; B1 = nB1; C0 = nC0; C1 = nC1; xv = nx; dtv = ndt;
    }
}

// ---------------- gated RMSNorm: y*silu(z), rmsnorm, *norm_w ---------------
__global__ __launch_bounds__(512) void k_gatedrms(const float* __restrict__ nw, int layer) {
    int dir = blockIdx.y;
    int m = blockIdx.x;
    int i = threadIdx.x;  // 0..511
    int li = dir*NLAYERS + layer;
    float yv = g_scratch[OFF_Y + (size_t)dir*M2*DI + (size_t)m*DI + i];
    float zv = g_scratch[OFF_ZX + (size_t)dir*M2*DIP + (size_t)m*DIP + i];
    float g = yv * (zv / (1.f + __expf(-zv)));
    float ss = g * g;
#pragma unroll
    for (int o = 16; o > 0; o >>= 1) ss += __shfl_xor_sync(0xffffffffu, ss, o);
    __shared__ float red[16];
    if ((i & 31) == 0) red[i >> 5] = ss;
    __syncthreads();
    if (i < 32) {
        float v = (i < 16) ? red[i] : 0.f;
#pragma unroll
        for (int o = 8; o > 0; o >>= 1) v += __shfl_xor_sync(0xffffffffu, v, o);
        if (i == 0) red[0] = v;
    }
    __syncthreads();
    float inv = rsqrtf(red[0] * (1.f/DI) + 1e-5f);
    g_scratch[OFF_NRM + (size_t)dir*M2*DI + (size_t)m*DI + i] = g * inv * nw[(size_t)li*DI + i];
}

// ---------------- combine fwd + flipped bwd --------------------------------
__global__ void k_comb() {
    int m = blockIdx.x;
    int i = threadIdx.x;  // 0..511
    int b = m / LSEQ, l = m % LSEQ;
    float v;
    if (i < DM) v = g_scratch[OFF_H + (size_t)m*DM + i];
    else        v = g_scratch[OFF_H + (size_t)M2*DM + ((size_t)b*LSEQ + (LSEQ-1-l))*DM + (i-DM)];
    g_scratch[OFF_COMB + (size_t)m*2*DM + i] = v;
}

// ---------------- gate sigmoid + fuse + LayerNorm --------------------------
__global__ __launch_bounds__(256) void k_final(const float* __restrict__ fb,
                                               const float* __restrict__ lnw,
                                               const float* __restrict__ lnb,
                                               float* __restrict__ out) {
    int m = blockIdx.x;
    int d = threadIdx.x;  // 0..255
    int b = m / LSEQ, l = m % LSEQ;
    float gl0 = g_scratch[OFF_GATE + (size_t)m*2*DM + d] + fb[d];
    float gl1 = g_scratch[OFF_GATE + (size_t)m*2*DM + DM + d] + fb[DM + d];
    float gf = 1.f / (1.f + __expf(-gl0));
    float gb = 1.f / (1.f + __expf(-gl1));
    float fwd = g_scratch[OFF_H + (size_t)m*DM + d];
    float bwd = g_scratch[OFF_H + (size_t)M2*DM + ((size_t)b*LSEQ + (LSEQ-1-l))*DM + d];
    float fu = gf*fwd + gb*bwd;

    float s1 = fu, s2 = fu*fu;
#pragma unroll
    for (int o = 16; o > 0; o >>= 1) {
        s1 += __shfl_xor_sync(0xffffffffu, s1, o);
        s2 += __shfl_xor_sync(0xffffffffu, s2, o);
    }
    __shared__ float r1[8], r2[8];
    if ((d & 31) == 0) { r1[d >> 5] = s1; r2[d >> 5] = s2; }
    __syncthreads();
    if (d < 32) {
        float v1 = (d < 8) ? r1[d] : 0.f;
        float v2 = (d < 8) ? r2[d] : 0.f;
#pragma unroll
        for (int o = 4; o > 0; o >>= 1) {
            v1 += __shfl_xor_sync(0xffffffffu, v1, o);
            v2 += __shfl_xor_sync(0xffffffffu, v2, o);
        }
        if (d == 0) { r1[0] = v1; r2[0] = v2; }
    }
    __syncthreads();
    float mu = r1[0] * (1.f/DM);
    float var = r2[0] * (1.f/DM) - mu*mu;
    float inv = rsqrtf(var + 1e-5f);
    out[(size_t)m*DM + d] = (fu - mu) * inv * lnw[d] + lnb[d];
}

// ---------------------------------------------------------------------------
extern "C" void kernel_launch(void* const* d_in, const int* in_sizes, int n_in,
                              void* d_out, int out_size) {
    const int*   ids  = (const int*)d_in[0];
    const float* mask = (const float*)d_in[1];
    const float* tok  = (const float*)d_in[2];
    const float* pos  = (const float*)d_in[3];
    const float* inw  = (const float*)d_in[4];
    const float* cw   = (const float*)d_in[5];
    const float* cb   = (const float*)d_in[6];
    const float* dtb  = (const float*)d_in[7];
    const float* alog = (const float*)d_in[8];
    const float* dpar = (const float*)d_in[9];
    const float* nw   = (const float*)d_in[10];
    const float* ow   = (const float*)d_in[11];
    const float* fw   = (const float*)d_in[12];
    const float* fb   = (const float*)d_in[13];
    const float* lnw  = (const float*)d_in[14];
    const float* lnb  = (const float*)d_in[15];

    float* scr = nullptr;
    cudaGetSymbolAddress((void**)&scr, g_scratch);
    float* pH    = scr + OFF_H;
    float* pZX   = scr + OFF_ZX;
    float* pNRM  = scr + OFF_NRM;
    float* pCOMB = scr + OFF_COMB;
    float* pGATE = scr + OFF_GATE;

    k_embed<<<M2, DM>>>(ids, mask, tok, pos);

    for (int layer = 0; layer < NLAYERS; layer++) {
        for (int dir = 0; dir < 2; dir++) {
            k_gemm_nt<<<dim3((DIP + 63) / 64, M2 / 64), 256>>>(
                pH + (size_t)dir*M2*DM,
                inw + (size_t)(dir*NLAYERS + layer)*DIP*DM,
                pZX + (size_t)dir*M2*DIP, M2, DIP, DM);
        }
        k_conv<<<dim3(M2, 2), CD>>>(cw, cb, dtb, layer);
        k_scan<<<128, 128>>>(alog, dpar, layer);
        k_gatedrms<<<dim3(M2, 2), DI>>>(nw, layer);
        for (int dir = 0; dir < 2; dir++) {
            k_gemm_nt<<<dim3(DM / 64, M2 / 64), 256>>>(
                pNRM + (size_t)dir*M2*DI,
                ow + (size_t)(dir*NLAYERS + layer)*DM*DI,
                pH + (size_t)dir*M2*DM, M2, DM, DI);
        }
    }

    k_comb<<<M2, 2*DM>>>();
    k_gemm_nt<<<dim3(2*DM / 64, M2 / 64), 256>>>(pCOMB, fw, pGATE, M2, 2*DM, 2*DM);
    k_final<<<M2, DM>>>(fb, lnw, lnb, (float*)d_out);
}

// round 2
// speedup vs baseline: 1.3645x; 1.3645x over previous
#include <cuda_runtime.h>
#include <math.h>

#define BB 2
#define LSEQ 1024
#define DM 256
#define DI 512
#define DS 64
#define NH 8
#define HD 64
#define CD 640
#define DIP 1160
#define M2 (BB*LSEQ)
#define NLAYERS 2
#define NCHUNK 16
#define QCH 64

static constexpr size_t OFF_H    = 0;
static constexpr size_t OFF_ZX   = OFF_H    + (size_t)2*M2*DM;
static constexpr size_t OFF_CONV = OFF_ZX   + (size_t)2*M2*DIP;
static constexpr size_t OFF_DT   = OFF_CONV + (size_t)2*M2*CD;
static constexpr size_t OFF_Y    = OFF_DT   + (size_t)2*M2*NH;
static constexpr size_t OFF_NRM  = OFF_Y    + (size_t)2*M2*DI;
static constexpr size_t OFF_COMB = OFF_NRM  + (size_t)2*M2*DI;
static constexpr size_t OFF_GATE = OFF_COMB + (size_t)M2*2*DM;
static constexpr size_t OFF_HLOC = OFF_GATE + (size_t)M2*2*DM;            // 32*16*64*64
static constexpr size_t OFF_SDT  = OFF_HLOC + (size_t)32*NCHUNK*HD*DS;    // 32*1024
static constexpr size_t OFF_CSUM = OFF_SDT  + (size_t)32*LSEQ;            // 32*16
static constexpr size_t SCRATCH_TOTAL = OFF_CSUM + (size_t)32*NCHUNK;

__device__ float g_scratch[SCRATCH_TOTAL];

// ---------------- embedding (writes fwd h and time-flipped bwd h) -----------
__global__ void k_embed(const int* __restrict__ ids, const float* __restrict__ mask,
                        const float* __restrict__ tok, const float* __restrict__ pos) {
    int bl = blockIdx.x;
    int d  = threadIdx.x;
    int b = bl / LSEQ, l = bl % LSEQ;
    int id = ids[bl];
    float v = (tok[(size_t)id*DM + d] + pos[(size_t)l*DM + d]) * mask[bl];
    g_scratch[OFF_H + (size_t)bl*DM + d] = v;
    g_scratch[OFF_H + (size_t)M2*DM + ((size_t)b*LSEQ + (LSEQ-1-l))*DM + d] = v;
}

// --------- C[M,N] = A[M,K] @ W[N,K]^T, 128x64 tile, double-buffered ---------
// 256 threads, 8x4 microtile. M%128==0, K%8==0, N%8==0. blockIdx.z batches.
__global__ __launch_bounds__(256) void k_gemm(
        const float* __restrict__ A, const float* __restrict__ W,
        float* __restrict__ C, int M, int N, int K,
        long sAz, long sWz, long sCz) {
    A += (long)blockIdx.z * sAz;
    W += (long)blockIdx.z * sWz;
    C += (long)blockIdx.z * sCz;
    __shared__ float As[2][8][128];
    __shared__ float Ws[2][8][64];
    int tid = threadIdx.x;
    int m0 = blockIdx.y * 128, n0 = blockIdx.x * 64;

    int ar = tid >> 1, ak = (tid & 1) * 4;          // A: 128 rows x 8k
    int wr = (tid >> 1) & 63, wk = (tid & 1) * 4;   // W: 64 rows x 8k (t<128)
    bool wload = tid < 128;
    bool wvalid = wload && (n0 + wr < N);

    int ty = tid >> 4, tx = tid & 15;               // 8 rows, 4 cols per thread

    float acc[8][4];
#pragma unroll
    for (int i = 0; i < 8; i++)
#pragma unroll
        for (int j = 0; j < 4; j++) acc[i][j] = 0.f;

    const float* Ap = A + (size_t)(m0 + ar)*K + ak;
    const float* Wp = W + (size_t)(n0 + wr)*K + wk;

    float4 ra = *(const float4*)Ap;
    float4 rw = wvalid ? *(const float4*)Wp : make_float4(0.f,0.f,0.f,0.f);
    As[0][ak+0][ar] = ra.x; As[0][ak+1][ar] = ra.y;
    As[0][ak+2][ar] = ra.z; As[0][ak+3][ar] = ra.w;
    if (wload) {
        Ws[0][wk+0][wr] = rw.x; Ws[0][wk+1][wr] = rw.y;
        Ws[0][wk+2][wr] = rw.z; Ws[0][wk+3][wr] = rw.w;
    }
    __syncthreads();

    int KT = K >> 3;
    int buf = 0;
    for (int kt = 0; kt < KT; kt++) {
        float4 na = make_float4(0.f,0.f,0.f,0.f);
        float4 nw = make_float4(0.f,0.f,0.f,0.f);
        if (kt + 1 < KT) {
            na = *(const float4*)(Ap + (kt+1)*8);
            if (wvalid) nw = *(const float4*)(Wp + (kt+1)*8);
        }
#pragma unroll
        for (int kk = 0; kk < 8; kk++) {
            float4 a0 = *(const float4*)&As[buf][kk][ty*8];
            float4 a1 = *(const float4*)&As[buf][kk][ty*8+4];
            float4 w  = *(const float4*)&Ws[buf][kk][tx*4];
            float av[8] = {a0.x,a0.y,a0.z,a0.w,a1.x,a1.y,a1.z,a1.w};
            float wv[4] = {w.x,w.y,w.z,w.w};
#pragma unroll
            for (int i = 0; i < 8; i++)
#pragma unroll
                for (int j = 0; j < 4; j++)
                    acc[i][j] += av[i]*wv[j];
        }
        if (kt + 1 < KT) {
            int nb = buf ^ 1;
            As[nb][ak+0][ar] = na.x; As[nb][ak+1][ar] = na.y;
            As[nb][ak+2][ar] = na.z; As[nb][ak+3][ar] = na.w;
            if (wload) {
                Ws[nb][wk+0][wr] = nw.x; Ws[nb][wk+1][wr] = nw.y;
                Ws[nb][wk+2][wr] = nw.z; Ws[nb][wk+3][wr] = nw.w;
            }
            __syncthreads();
            buf = nb;
        }
    }

    int n = n0 + tx*4;
    if (n < N) {
#pragma unroll
        for (int i = 0; i < 8; i++) {
            int m = m0 + ty*8 + i;
            *(float4*)(C + (size_t)m*N + n) =
                make_float4(acc[i][0], acc[i][1], acc[i][2], acc[i][3]);
        }
    }
}

// ---------------- depthwise causal conv(4) + SiLU + dt softplus -------------
__global__ void k_conv(const float* __restrict__ cw, const float* __restrict__ cbias,
                       const float* __restrict__ dtb, int layer) {
    int dir = blockIdx.y;
    int bl = blockIdx.x;
    int b = bl / LSEQ, l = bl % LSEQ;
    int c = threadIdx.x;
    int li = dir*NLAYERS + layer;
    const float* zx = g_scratch + OFF_ZX + (size_t)dir*M2*DIP;
    float4 w = *(const float4*)(cw + ((size_t)li*CD + c)*4);
    float wk[4] = {w.x, w.y, w.z, w.w};
    float acc = 0.f;
#pragma unroll
    for (int k = 0; k < 4; k++) {
        int ls = l - 3 + k;
        if (ls >= 0)
            acc += zx[((size_t)b*LSEQ + ls)*DIP + DI + c] * wk[k];
    }
    acc += cbias[(size_t)li*CD + c];
    float s = acc / (1.f + __expf(-acc));
    g_scratch[OFF_CONV + (size_t)dir*M2*CD + (size_t)bl*CD + c] = s;
    if (c < NH) {
        float raw = zx[(size_t)bl*DIP + DI + CD + c] + dtb[li*NH + c];
        float sp = (raw > 20.f) ? raw : log1pf(expf(raw));
        g_scratch[OFF_DT + (size_t)dir*M2*NH + (size_t)bl*NH + c] = sp;
    }
}

// ---------------- scan pass 1: intra-chunk scan from zero state -------------
// grid: (dir,b,head,pg,chunk) = 2*2*8*4*16 = 2048 blocks, 128 threads.
__global__ __launch_bounds__(128) void k_scan1(const float* __restrict__ A_log,
                                               const float* __restrict__ Dp, int layer) {
    int idx = blockIdx.x;
    int chunk = idx & 15; idx >>= 4;
    int pg = idx & 3; idx >>= 2;
    int hh = idx & 7; idx >>= 3;
    int b = idx & 1; int dir = idx >> 1;
    int hg = (dir*2 + b)*8 + hh;
    int t = threadIdx.x;
    int ql = t & 7, pl = t >> 3;
    int p = pg*16 + pl;
    int n0 = ql*8;
    int li = dir*NLAYERS + layer;
    float Aa = -expf(A_log[li*NH + hh]);
    float Dv = Dp[li*NH + hh];
    const float* conv = g_scratch + OFF_CONV + (size_t)dir*M2*CD + (size_t)b*LSEQ*CD;
    const float* dt   = g_scratch + OFF_DT   + (size_t)dir*M2*NH + (size_t)b*LSEQ*NH;
    float* y          = g_scratch + OFF_Y    + (size_t)dir*M2*DI + (size_t)b*LSEQ*DI;
    float* sdt        = g_scratch + OFF_SDT  + (size_t)hg*LSEQ;

    float h[8];
#pragma unroll
    for (int j = 0; j < 8; j++) h[j] = 0.f;
    float sum = 0.f;
    int s0 = chunk * QCH;

    for (int j = 0; j < QCH; j++) {
        int s = s0 + j;
        const float* cr = conv + (size_t)s*CD;
        float4 B0 = *(const float4*)(cr + DI + n0);
        float4 B1 = *(const float4*)(cr + DI + n0 + 4);
        float4 C0 = *(const float4*)(cr + DI + DS + n0);
        float4 C1 = *(const float4*)(cr + DI + DS + n0 + 4);
        float xv  = cr[hh*HD + p];
        float dtv = dt[(size_t)s*NH + hh];

        float dA = __expf(dtv * Aa);
        float sc = dtv * xv;
        float acc;
        h[0] = h[0]*dA + sc*B0.x; acc  = h[0]*C0.x;
        h[1] = h[1]*dA + sc*B0.y; acc += h[1]*C0.y;
        h[2] = h[2]*dA + sc*B0.z; acc += h[2]*C0.z;
        h[3] = h[3]*dA + sc*B0.w; acc += h[3]*C0.w;
        h[4] = h[4]*dA + sc*B1.x; acc += h[4]*C1.x;
        h[5] = h[5]*dA + sc*B1.y; acc += h[5]*C1.y;
        h[6] = h[6]*dA + sc*B1.z; acc += h[6]*C1.z;
        h[7] = h[7]*dA + sc*B1.w; acc += h[7]*C1.w;

        acc += __shfl_xor_sync(0xffffffffu, acc, 1);
        acc += __shfl_xor_sync(0xffffffffu, acc, 2);
        acc += __shfl_xor_sync(0xffffffffu, acc, 4);
        if (ql == 0) y[(size_t)s*DI + hh*HD + p] = acc + Dv*xv;

        sum += dtv;
        if (t == 0 && pg == 0) sdt[s] = sum;
    }
    if (t == 0 && pg == 0) g_scratch[OFF_CSUM + hg*NCHUNK + chunk] = sum;

    float* hl = g_scratch + OFF_HLOC + ((size_t)hg*NCHUNK + chunk)*(HD*DS)
              + (size_t)p*DS + n0;
    *(float4*)hl     = make_float4(h[0], h[1], h[2], h[3]);
    *(float4*)(hl+4) = make_float4(h[4], h[5], h[6], h[7]);
}

// ---------------- scan pass 2: inter-chunk state carry ----------------------
// grid 512 (32 hg x 16), 256 threads; each thread owns one (p,n) element.
__global__ __launch_bounds__(256) void k_scan2(const float* __restrict__ A_log, int layer) {
    int hg = blockIdx.x >> 4;
    int e  = (blockIdx.x & 15)*256 + threadIdx.x;   // 0..4095
    int dir = hg >> 4, hh = hg & 7;
    int li = dir*NLAYERS + layer;
    float Aa = -expf(A_log[li*NH + hh]);
    const float* csum = g_scratch + OFF_CSUM + hg*NCHUNK;
    float* hl = g_scratch + OFF_HLOC + (size_t)hg*NCHUNK*(HD*DS) + e;
    float tmp[NCHUNK];
#pragma unroll
    for (int c = 0; c < NCHUNK; c++) tmp[c] = hl[(size_t)c*(HD*DS)];
    float carry = 0.f;
#pragma unroll
    for (int c = 0; c < NCHUNK; c++) {
        hl[(size_t)c*(HD*DS)] = carry;                 // incoming state for chunk c
        carry = carry * __expf(Aa * csum[c]) + tmp[c];
    }
}

// ---------------- scan pass 3: add C·(cumdecay·h_in) ------------------------
__global__ __launch_bounds__(128) void k_scan3(const float* __restrict__ A_log, int layer) {
    int idx = blockIdx.x;
    int chunk = idx & 15; idx >>= 4;
    if (chunk == 0) return;
    int pg = idx & 3; idx >>= 2;
    int hh = idx & 7; idx >>= 3;
    int b = idx & 1; int dir = idx >> 1;
    int hg = (dir*2 + b)*8 + hh;
    int t = threadIdx.x;
    int ql = t & 7, pl = t >> 3;
    int p = pg*16 + pl;
    int n0 = ql*8;
    int li = dir*NLAYERS + layer;
    float Aa = -expf(A_log[li*NH + hh]);
    const float* conv = g_scratch + OFF_CONV + (size_t)dir*M2*CD + (size_t)b*LSEQ*CD;
    float* y          = g_scratch + OFF_Y    + (size_t)dir*M2*DI + (size_t)b*LSEQ*DI;
    const float* sdt  = g_scratch + OFF_SDT  + (size_t)hg*LSEQ;
    const float* hl   = g_scratch + OFF_HLOC + ((size_t)hg*NCHUNK + chunk)*(HD*DS)
                      + (size_t)p*DS + n0;
    float4 h0 = *(const float4*)hl;
    float4 h1 = *(const float4*)(hl + 4);
    int s0 = chunk * QCH;
    for (int j = 0; j < QCH; j++) {
        int s = s0 + j;
        const float* cr = conv + (size_t)s*CD + DI + DS + n0;
        float4 C0 = *(const float4*)cr;
        float4 C1 = *(const float4*)(cr + 4);
        float cum = __expf(Aa * sdt[s]);
        float acc = h0.x*C0.x + h0.y*C0.y + h0.z*C0.z + h0.w*C0.w
                  + h1.x*C1.x + h1.y*C1.y + h1.z*C1.z + h1.w*C1.w;
        acc += __shfl_xor_sync(0xffffffffu, acc, 1);
        acc += __shfl_xor_sync(0xffffffffu, acc, 2);
        acc += __shfl_xor_sync(0xffffffffu, acc, 4);
        if (ql == 0) y[(size_t)s*DI + hh*HD + p] += cum * acc;
    }
}

// ---------------- gated RMSNorm ---------------------------------------------
__global__ __launch_bounds__(512) void k_gatedrms(const float* __restrict__ nw, int layer) {
    int dir = blockIdx.y;
    int m = blockIdx.x;
    int i = threadIdx.x;
    int li = dir*NLAYERS + layer;
    float yv = g_scratch[OFF_Y + (size_t)dir*M2*DI + (size_t)m*DI + i];
    float zv = g_scratch[OFF_ZX + (size_t)dir*M2*DIP + (size_t)m*DIP + i];
    float g = yv * (zv / (1.f + __expf(-zv)));
    float ss = g * g;
#pragma unroll
    for (int o = 16; o > 0; o >>= 1) ss += __shfl_xor_sync(0xffffffffu, ss, o);
    __shared__ float red[16];
    if ((i & 31) == 0) red[i >> 5] = ss;
    __syncthreads();
    if (i < 32) {
        float v = (i < 16) ? red[i] : 0.f;
#pragma unroll
        for (int o = 8; o > 0; o >>= 1) v += __shfl_xor_sync(0xffffffffu, v, o);
        if (i == 0) red[0] = v;
    }
    __syncthreads();
    float inv = rsqrtf(red[0] * (1.f/DI) + 1e-5f);
    g_scratch[OFF_NRM + (size_t)dir*M2*DI + (size_t)m*DI + i] = g * inv * nw[(size_t)li*DI + i];
}

// ---------------- combine fwd + flipped bwd ---------------------------------
__global__ void k_comb() {
    int m = blockIdx.x;
    int i = threadIdx.x;
    int b = m / LSEQ, l = m % LSEQ;
    float v;
    if (i < DM) v = g_scratch[OFF_H + (size_t)m*DM + i];
    else        v = g_scratch[OFF_H + (size_t)M2*DM + ((size_t)b*LSEQ + (LSEQ-1-l))*DM + (i-DM)];
    g_scratch[OFF_COMB + (size_t)m*2*DM + i] = v;
}

// ---------------- gate sigmoid + fuse + LayerNorm ---------------------------
__global__ __launch_bounds__(256) void k_final(const float* __restrict__ fb,
                                               const float* __restrict__ lnw,
                                               const float* __restrict__ lnb,
                                               float* __restrict__ out) {
    int m = blockIdx.x;
    int d = threadIdx.x;
    int b = m / LSEQ, l = m % LSEQ;
    float gl0 = g_scratch[OFF_GATE + (size_t)m*2*DM + d] + fb[d];
    float gl1 = g_scratch[OFF_GATE + (size_t)m*2*DM + DM + d] + fb[DM + d];
    float gf = 1.f / (1.f + __expf(-gl0));
    float gb = 1.f / (1.f + __expf(-gl1));
    float fwd = g_scratch[OFF_H + (size_t)m*DM + d];
    float bwd = g_scratch[OFF_H + (size_t)M2*DM + ((size_t)b*LSEQ + (LSEQ-1-l))*DM + d];
    float fu = gf*fwd + gb*bwd;

    float s1 = fu, s2 = fu*fu;
#pragma unroll
    for (int o = 16; o > 0; o >>= 1) {
        s1 += __shfl_xor_sync(0xffffffffu, s1, o);
        s2 += __shfl_xor_sync(0xffffffffu, s2, o);
    }
    __shared__ float r1[8], r2[8];
    if ((d & 31) == 0) { r1[d >> 5] = s1; r2[d >> 5] = s2; }
    __syncthreads();
    if (d < 32) {
        float v1 = (d < 8) ? r1[d] : 0.f;
        float v2 = (d < 8) ? r2[d] : 0.f;
#pragma unroll
        for (int o = 4; o > 0; o >>= 1) {
            v1 += __shfl_xor_sync(0xffffffffu, v1, o);
            v2 += __shfl_xor_sync(0xffffffffu, v2, o);
        }
        if (d == 0) { r1[0] = v1; r2[0] = v2; }
    }
    __syncthreads();
    float mu = r1[0] * (1.f/DM);
    float var = r2[0] * (1.f/DM) - mu*mu;
    float inv = rsqrtf(var + 1e-5f);
    out[(size_t)m*DM + d] = (fu - mu) * inv * lnw[d] + lnb[d];
}

// ---------------------------------------------------------------------------
extern "C" void kernel_launch(void* const* d_in, const int* in_sizes, int n_in,
                              void* d_out, int out_size) {
    const int*   ids  = (const int*)d_in[0];
    const float* mask = (const float*)d_in[1];
    const float* tok  = (const float*)d_in[2];
    const float* pos  = (const float*)d_in[3];
    const float* inw  = (const float*)d_in[4];
    const float* cw   = (const float*)d_in[5];
    const float* cb   = (const float*)d_in[6];
    const float* dtb  = (const float*)d_in[7];
    const float* alog = (const float*)d_in[8];
    const float* dpar = (const float*)d_in[9];
    const float* nw   = (const float*)d_in[10];
    const float* ow   = (const float*)d_in[11];
    const float* fw   = (const float*)d_in[12];
    const float* fb   = (const float*)d_in[13];
    const float* lnw  = (const float*)d_in[14];
    const float* lnb  = (const float*)d_in[15];

    float* scr = nullptr;
    cudaGetSymbolAddress((void**)&scr, g_scratch);
    float* pH    = scr + OFF_H;
    float* pZX   = scr + OFF_ZX;
    float* pNRM  = scr + OFF_NRM;
    float* pCOMB = scr + OFF_COMB;
    float* pGATE = scr + OFF_GATE;

    k_embed<<<M2, DM>>>(ids, mask, tok, pos);

    for (int layer = 0; layer < NLAYERS; layer++) {
        // in_proj for both dirs: C[M2, DIP] = H @ inw^T
        k_gemm<<<dim3((DIP + 63)/64, M2/128, 2), 256>>>(
            pH, inw + (size_t)layer*DIP*DM, pZX, M2, DIP, DM,
            (long)M2*DM, (long)NLAYERS*DIP*DM, (long)M2*DIP);
        k_conv<<<dim3(M2, 2), CD>>>(cw, cb, dtb, layer);
        k_scan1<<<2048, 128>>>(alog, dpar, layer);
        k_scan2<<<512, 256>>>(alog, layer);
        k_scan3<<<2048, 128>>>(alog, layer);
        k_gatedrms<<<dim3(M2, 2), DI>>>(nw, layer);
        // out_proj for both dirs
        k_gemm<<<dim3(DM/64, M2/128, 2), 256>>>(
            pNRM, ow + (size_t)layer*DM*DI, pH, M2, DM, DI,
            (long)M2*DI, (long)NLAYERS*DM*DI, (long)M2*DM);
    }

    k_comb<<<M2, 2*DM>>>();
    k_gemm<<<dim3(2*DM/64, M2/128, 1), 256>>>(pCOMB, fw, pGATE, M2, 2*DM, 2*DM, 0, 0, 0);
    k_final<<<M2, DM>>>(fb, lnw, lnb, (float*)d_out);
}

// round 3
// speedup vs baseline: 1.5252x; 1.1177x over previous
#include <cuda_runtime.h>
#include <math.h>

#define BB 2
#define LSEQ 1024
#define DM 256
#define DI 512
#define DS 64
#define NH 8
#define HD 64
#define CD 640
#define DIP 1160
#define M2 (BB*LSEQ)
#define NLAYERS 2
#define NCHUNK 16
#define QCH 64

static constexpr size_t OFF_H    = 0;
static constexpr size_t OFF_ZX   = OFF_H    + (size_t)2*M2*DM;
static constexpr size_t OFF_CONV = OFF_ZX   + (size_t)2*M2*DIP;
static constexpr size_t OFF_DT   = OFF_CONV + (size_t)2*M2*CD;
static constexpr size_t OFF_Y    = OFF_DT   + (size_t)2*M2*NH;
static constexpr size_t OFF_NRM  = OFF_Y    + (size_t)2*M2*DI;
static constexpr size_t OFF_COMB = OFF_NRM  + (size_t)2*M2*DI;
static constexpr size_t OFF_GATE = OFF_COMB + (size_t)M2*2*DM;
static constexpr size_t OFF_HLOC = OFF_GATE + (size_t)M2*2*DM;
static constexpr size_t OFF_SDT  = OFF_HLOC + (size_t)32*NCHUNK*HD*DS;
static constexpr size_t OFF_CSUM = OFF_SDT  + (size_t)32*LSEQ;
static constexpr size_t SCRATCH_TOTAL = OFF_CSUM + (size_t)32*NCHUNK;

__device__ float g_scratch[SCRATCH_TOTAL];

typedef unsigned long long ull;

// ---- packed fp32x2 helpers (PTX-only on sm_103a; ptxas never emits FFMA2) --
__device__ __forceinline__ ull pk2(float a, float b) {
    ull r;
    asm("mov.b64 %0, {%1, %2};" : "=l"(r) : "r"(__float_as_int(a)), "r"(__float_as_int(b)));
    return r;
}
__device__ __forceinline__ void upk2(ull v, float& a, float& b) {
    unsigned int x, y;
    asm("mov.b64 {%0, %1}, %2;" : "=r"(x), "=r"(y) : "l"(v));
    a = __int_as_float(x); b = __int_as_float(y);
}
__device__ __forceinline__ void fma2(ull& d, ull a, ull b) {
    asm("fma.rn.f32x2 %0, %1, %2, %0;" : "+l"(d) : "l"(a), "l"(b));
}
__device__ __forceinline__ ull mul2(ull a, ull b) {
    ull r; asm("mul.rn.f32x2 %0, %1, %2;" : "=l"(r) : "l"(a), "l"(b)); return r;
}

// ---------------- embedding -------------------------------------------------
__global__ void k_embed(const int* __restrict__ ids, const float* __restrict__ mask,
                        const float* __restrict__ tok, const float* __restrict__ pos) {
    int bl = blockIdx.x;
    int d  = threadIdx.x;
    int b = bl / LSEQ, l = bl % LSEQ;
    int id = ids[bl];
    float v = (tok[(size_t)id*DM + d] + pos[(size_t)l*DM + d]) * mask[bl];
    g_scratch[OFF_H + (size_t)bl*DM + d] = v;
    g_scratch[OFF_H + (size_t)M2*DM + ((size_t)b*LSEQ + (LSEQ-1-l))*DM + d] = v;
}

// --------- C[M,N] = A[M,K] @ W[N,K]^T, 128x64 tile, f32x2 inner -------------
__global__ __launch_bounds__(256) void k_gemm(
        const float* __restrict__ A, const float* __restrict__ W,
        float* __restrict__ C, int M, int N, int K,
        long sAz, long sWz, long sCz) {
    A += (long)blockIdx.z * sAz;
    W += (long)blockIdx.z * sWz;
    C += (long)blockIdx.z * sCz;
    __shared__ float As[2][8][128];
    __shared__ float Ws[2][8][64];
    int tid = threadIdx.x;
    int m0 = blockIdx.y * 128, n0 = blockIdx.x * 64;

    int ar = tid >> 1, ak = (tid & 1) * 4;
    int wr = (tid >> 1) & 63, wk = (tid & 1) * 4;
    bool wload = tid < 128;
    bool wvalid = wload && (n0 + wr < N);

    int ty = tid >> 4, tx = tid & 15;

    ull acc2[4][4];
#pragma unroll
    for (int i = 0; i < 4; i++)
#pragma unroll
        for (int j = 0; j < 4; j++) acc2[i][j] = 0ULL;

    const float* Ap = A + (size_t)(m0 + ar)*K + ak;
    const float* Wp = W + (size_t)(n0 + wr)*K + wk;

    float4 ra = *(const float4*)Ap;
    float4 rw = wvalid ? *(const float4*)Wp : make_float4(0.f,0.f,0.f,0.f);
    As[0][ak+0][ar] = ra.x; As[0][ak+1][ar] = ra.y;
    As[0][ak+2][ar] = ra.z; As[0][ak+3][ar] = ra.w;
    if (wload) {
        Ws[0][wk+0][wr] = rw.x; Ws[0][wk+1][wr] = rw.y;
        Ws[0][wk+2][wr] = rw.z; Ws[0][wk+3][wr] = rw.w;
    }
    __syncthreads();

    int KT = K >> 3;
    int buf = 0;
    for (int kt = 0; kt < KT; kt++) {
        float4 na = make_float4(0.f,0.f,0.f,0.f);
        float4 nw = make_float4(0.f,0.f,0.f,0.f);
        if (kt + 1 < KT) {
            na = *(const float4*)(Ap + (kt+1)*8);
            if (wvalid) nw = *(const float4*)(Wp + (kt+1)*8);
        }
#pragma unroll
        for (int kk = 0; kk < 8; kk++) {
            const ulonglong2* pa = (const ulonglong2*)&As[buf][kk][ty*8];
            ulonglong2 aA = pa[0], aB = pa[1];
            ull av2[4] = {aA.x, aA.y, aB.x, aB.y};
            float4 w = *(const float4*)&Ws[buf][kk][tx*4];
            ull w2[4] = {pk2(w.x,w.x), pk2(w.y,w.y), pk2(w.z,w.z), pk2(w.w,w.w)};
#pragma unroll
            for (int i = 0; i < 4; i++)
#pragma unroll
                for (int j = 0; j < 4; j++)
                    fma2(acc2[i][j], av2[i], w2[j]);
        }
        if (kt + 1 < KT) {
            int nb = buf ^ 1;
            As[nb][ak+0][ar] = na.x; As[nb][ak+1][ar] = na.y;
            As[nb][ak+2][ar] = na.z; As[nb][ak+3][ar] = na.w;
            if (wload) {
                Ws[nb][wk+0][wr] = nw.x; Ws[nb][wk+1][wr] = nw.y;
                Ws[nb][wk+2][wr] = nw.z; Ws[nb][wk+3][wr] = nw.w;
            }
            __syncthreads();
            buf = nb;
        }
    }

    int n = n0 + tx*4;
    if (n < N) {
#pragma unroll
        for (int ip = 0; ip < 4; ip++) {
            float r0[4], r1[4];
#pragma unroll
            for (int j = 0; j < 4; j++) upk2(acc2[ip][j], r0[j], r1[j]);
            int m = m0 + ty*8 + 2*ip;
            *(float4*)(C + (size_t)m*N + n)     = make_float4(r0[0], r0[1], r0[2], r0[3]);
            *(float4*)(C + (size_t)(m+1)*N + n) = make_float4(r1[0], r1[1], r1[2], r1[3]);
        }
    }
}

// ---------------- depthwise causal conv(4) + SiLU + dt softplus -------------
__global__ void k_conv(const float* __restrict__ cw, const float* __restrict__ cbias,
                       const float* __restrict__ dtb, int layer) {
    int dir = blockIdx.y;
    int bl = blockIdx.x;
    int b = bl / LSEQ, l = bl % LSEQ;
    int c = threadIdx.x;
    int li = dir*NLAYERS + layer;
    const float* zx = g_scratch + OFF_ZX + (size_t)dir*M2*DIP;
    float4 w = *(const float4*)(cw + ((size_t)li*CD + c)*4);
    float wk[4] = {w.x, w.y, w.z, w.w};
    float acc = 0.f;
#pragma unroll
    for (int k = 0; k < 4; k++) {
        int ls = l - 3 + k;
        if (ls >= 0)
            acc += zx[((size_t)b*LSEQ + ls)*DIP + DI + c] * wk[k];
    }
    acc += cbias[(size_t)li*CD + c];
    float s = acc / (1.f + __expf(-acc));
    g_scratch[OFF_CONV + (size_t)dir*M2*CD + (size_t)bl*CD + c] = s;
    if (c < NH) {
        float raw = zx[(size_t)bl*DIP + DI + CD + c] + dtb[li*NH + c];
        float sp = (raw > 20.f) ? raw : log1pf(expf(raw));
        g_scratch[OFF_DT + (size_t)dir*M2*NH + (size_t)bl*NH + c] = sp;
    }
}

// ---------------- scan pass 1: intra-chunk, smem-staged, f32x2 --------------
// grid (dir,b,head,chunk)=512 blocks, 256 thr. thread: ql=tid&3 (16 n's), p=tid>>2.
__global__ __launch_bounds__(256) void k_scan1(const float* __restrict__ A_log,
                                               const float* __restrict__ Dp, int layer) {
    int idx = blockIdx.x;
    int chunk = idx & 15; idx >>= 4;
    int hh = idx & 7; idx >>= 3;
    int b = idx & 1; int dir = idx >> 1;
    int hg = (dir*2 + b)*8 + hh;
    int tid = threadIdx.x;
    int ql = tid & 3, p = tid >> 2;
    int li = dir*NLAYERS + layer;
    float Aa = -expf(A_log[li*NH + hh]);
    float Dv = Dp[li*NH + hh];
    const float* conv = g_scratch + OFF_CONV + (size_t)dir*M2*CD + (size_t)b*LSEQ*CD;
    const float* dt   = g_scratch + OFF_DT   + (size_t)dir*M2*NH + (size_t)b*LSEQ*NH;
    float* y          = g_scratch + OFF_Y    + (size_t)dir*M2*DI + (size_t)b*LSEQ*DI;
    float* sdt_g      = g_scratch + OFF_SDT  + (size_t)hg*LSEQ;

    __shared__ float sB[16][64];
    __shared__ float sC[16][64];
    __shared__ float sx[16][64];
    __shared__ float sdt[16];

    ull h2[8];
#pragma unroll
    for (int k = 0; k < 8; k++) h2[k] = 0ULL;
    float runsum = 0.f;

    int js = tid >> 4, c4 = (tid & 15) * 4;   // staging map: step js, 4 cols

    for (int t = 0; t < 4; t++) {
        int s0 = chunk*QCH + t*16;
        {   // stage 16 steps
            const float* cr = conv + (size_t)(s0 + js)*CD;
            *(float4*)&sB[js][c4] = *(const float4*)(cr + DI + c4);
            *(float4*)&sC[js][c4] = *(const float4*)(cr + DI + DS + c4);
            *(float4*)&sx[js][c4] = *(const float4*)(cr + hh*HD + c4);
            if (tid < 16) sdt[tid] = dt[(size_t)(s0 + tid)*NH + hh];
        }
        __syncthreads();
        if (tid == 0) {   // chunk-local dt prefix (overlaps with compute)
            float rs = runsum;
#pragma unroll
            for (int j = 0; j < 16; j++) { rs += sdt[j]; sdt_g[s0 + j] = rs; }
            runsum = rs;
        }
#pragma unroll 4
        for (int j = 0; j < 16; j++) {
            float dtv = sdt[j];
            float dA = __expf(dtv * Aa);
            float xv = sx[j][p];
            float sc = dtv * xv;
            ull dA2 = pk2(dA, dA), sc2 = pk2(sc, sc);
            const ulonglong2* pB = (const ulonglong2*)&sB[j][ql*16];
            const ulonglong2* pC = (const ulonglong2*)&sC[j][ql*16];
            ulonglong2 b01 = pB[0], b23 = pB[1], b45 = pB[2], b67 = pB[3];
            ulonglong2 c01 = pC[0], c23 = pC[1], c45 = pC[2], c67 = pC[3];
            ull Bv[8] = {b01.x,b01.y,b23.x,b23.y,b45.x,b45.y,b67.x,b67.y};
            ull Cv[8] = {c01.x,c01.y,c23.x,c23.y,c45.x,c45.y,c67.x,c67.y};
            ull acc2 = 0ULL;
#pragma unroll
            for (int k = 0; k < 8; k++) {
                ull tmp = mul2(sc2, Bv[k]);
                fma2(h2[k], dA2, tmp);
                fma2(acc2, h2[k], Cv[k]);
            }
            float alo, ahi; upk2(acc2, alo, ahi);
            float acc = alo + ahi;
            acc += __shfl_xor_sync(0xffffffffu, acc, 1);
            acc += __shfl_xor_sync(0xffffffffu, acc, 2);
            if (ql == 0) y[(size_t)(s0 + j)*DI + hh*HD + p] = acc + Dv*xv;
        }
        __syncthreads();
    }
    if (tid == 0) g_scratch[OFF_CSUM + hg*NCHUNK + chunk] = runsum;

    float* hl = g_scratch + OFF_HLOC + ((size_t)hg*NCHUNK + chunk)*(HD*DS)
              + (size_t)p*DS + ql*16;
    ((ulonglong2*)hl)[0] = make_ulonglong2(h2[0], h2[1]);
    ((ulonglong2*)hl)[1] = make_ulonglong2(h2[2], h2[3]);
    ((ulonglong2*)hl)[2] = make_ulonglong2(h2[4], h2[5]);
    ((ulonglong2*)hl)[3] = make_ulonglong2(h2[6], h2[7]);
}

// ---------------- scan pass 2: inter-chunk state carry ----------------------
__global__ __launch_bounds__(256) void k_scan2(const float* __restrict__ A_log, int layer) {
    int hg = blockIdx.x >> 4;
    int e  = (blockIdx.x & 15)*256 + threadIdx.x;
    int dir = hg >> 4, hh = hg & 7;
    int li = dir*NLAYERS + layer;
    float Aa = -expf(A_log[li*NH + hh]);
    const float* csum = g_scratch + OFF_CSUM + hg*NCHUNK;
    float* hl = g_scratch + OFF_HLOC + (size_t)hg*NCHUNK*(HD*DS) + e;
    float tmp[NCHUNK];
#pragma unroll
    for (int c = 0; c < NCHUNK; c++) tmp[c] = hl[(size_t)c*(HD*DS)];
    float carry = 0.f;
#pragma unroll
    for (int c = 0; c < NCHUNK; c++) {
        hl[(size_t)c*(HD*DS)] = carry;
        carry = carry * __expf(Aa * csum[c]) + tmp[c];
    }
}

// ---------------- scan pass 3: y += exp(Aa*prefix) * (C·h_in) ---------------
__global__ __launch_bounds__(256) void k_scan3(const float* __restrict__ A_log, int layer) {
    int idx = blockIdx.x;
    int chunk = idx & 15; idx >>= 4;
    if (chunk == 0) return;
    int hh = idx & 7; idx >>= 3;
    int b = idx & 1; int dir = idx >> 1;
    int hg = (dir*2 + b)*8 + hh;
    int tid = threadIdx.x;
    int ql = tid & 3, p = tid >> 2;
    int li = dir*NLAYERS + layer;
    float Aa = -expf(A_log[li*NH + hh]);
    const float* conv = g_scratch + OFF_CONV + (size_t)dir*M2*CD + (size_t)b*LSEQ*CD;
    float* y          = g_scratch + OFF_Y    + (size_t)dir*M2*DI + (size_t)b*LSEQ*DI;
    const float* sdt_g= g_scratch + OFF_SDT  + (size_t)hg*LSEQ;
    const float* hl   = g_scratch + OFF_HLOC + ((size_t)hg*NCHUNK + chunk)*(HD*DS)
                      + (size_t)p*DS + ql*16;
    ulonglong2 h01 = ((const ulonglong2*)hl)[0];
    ulonglong2 h23 = ((const ulonglong2*)hl)[1];
    ulonglong2 h45 = ((const ulonglong2*)hl)[2];
    ulonglong2 h67 = ((const ulonglong2*)hl)[3];
    ull Hv[8] = {h01.x,h01.y,h23.x,h23.y,h45.x,h45.y,h67.x,h67.y};

    __shared__ float sC[16][64];
    __shared__ float sdt[16];
    int js = tid >> 4, c4 = (tid & 15) * 4;

    for (int t = 0; t < 4; t++) {
        int s0 = chunk*QCH + t*16;
        {
            const float* cr = conv + (size_t)(s0 + js)*CD;
            *(float4*)&sC[js][c4] = *(const float4*)(cr + DI + DS + c4);
            if (tid < 16) sdt[tid] = sdt_g[s0 + tid];
        }
        __syncthreads();
#pragma unroll 4
        for (int j = 0; j < 16; j++) {
            const ulonglong2* pC = (const ulonglong2*)&sC[j][ql*16];
            ulonglong2 c01 = pC[0], c23 = pC[1], c45 = pC[2], c67 = pC[3];
            ull Cv[8] = {c01.x,c01.y,c23.x,c23.y,c45.x,c45.y,c67.x,c67.y};
            ull acc2 = 0ULL;
#pragma unroll
            for (int k = 0; k < 8; k++) fma2(acc2, Hv[k], Cv[k]);
            float alo, ahi; upk2(acc2, alo, ahi);
            float acc = alo + ahi;
            acc += __shfl_xor_sync(0xffffffffu, acc, 1);
            acc += __shfl_xor_sync(0xffffffffu, acc, 2);
            if (ql == 0) {
                float cum = __expf(Aa * sdt[j]);
                y[(size_t)(s0 + j)*DI + hh*HD + p] += cum * acc;
            }
        }
        __syncthreads();
    }
}

// ---------------- gated RMSNorm ---------------------------------------------
__global__ __launch_bounds__(512) void k_gatedrms(const float* __restrict__ nw, int layer) {
    int dir = blockIdx.y;
    int m = blockIdx.x;
    int i = threadIdx.x;
    int li = dir*NLAYERS + layer;
    float yv = g_scratch[OFF_Y + (size_t)dir*M2*DI + (size_t)m*DI + i];
    float zv = g_scratch[OFF_ZX + (size_t)dir*M2*DIP + (size_t)m*DIP + i];
    float g = yv * (zv / (1.f + __expf(-zv)));
    float ss = g * g;
#pragma unroll
    for (int o = 16; o > 0; o >>= 1) ss += __shfl_xor_sync(0xffffffffu, ss, o);
    __shared__ float red[16];
    if ((i & 31) == 0) red[i >> 5] = ss;
    __syncthreads();
    if (i < 32) {
        float v = (i < 16) ? red[i] : 0.f;
#pragma unroll
        for (int o = 8; o > 0; o >>= 1) v += __shfl_xor_sync(0xffffffffu, v, o);
        if (i == 0) red[0] = v;
    }
    __syncthreads();
    float inv = rsqrtf(red[0] * (1.f/DI) + 1e-5f);
    g_scratch[OFF_NRM + (size_t)dir*M2*DI + (size_t)m*DI + i] = g * inv * nw[(size_t)li*DI + i];
}

// ---------------- combine fwd + flipped bwd ---------------------------------
__global__ void k_comb() {
    int m = blockIdx.x;
    int i = threadIdx.x;
    int b = m / LSEQ, l = m % LSEQ;
    float v;
    if (i < DM) v = g_scratch[OFF_H + (size_t)m*DM + i];
    else        v = g_scratch[OFF_H + (size_t)M2*DM + ((size_t)b*LSEQ + (LSEQ-1-l))*DM + (i-DM)];
    g_scratch[OFF_COMB + (size_t)m*2*DM + i] = v;
}

// ---------------- gate sigmoid + fuse + LayerNorm ---------------------------
__global__ __launch_bounds__(256) void k_final(const float* __restrict__ fb,
                                               const float* __restrict__ lnw,
                                               const float* __restrict__ lnb,
                                               float* __restrict__ out) {
    int m = blockIdx.x;
    int d = threadIdx.x;
    int b = m / LSEQ, l = m % LSEQ;
    float gl0 = g_scratch[OFF_GATE + (size_t)m*2*DM + d] + fb[d];
    float gl1 = g_scratch[OFF_GATE + (size_t)m*2*DM + DM + d] + fb[DM + d];
    float gf = 1.f / (1.f + __expf(-gl0));
    float gb = 1.f / (1.f + __expf(-gl1));
    float fwd = g_scratch[OFF_H + (size_t)m*DM + d];
    float bwd = g_scratch[OFF_H + (size_t)M2*DM + ((size_t)b*LSEQ + (LSEQ-1-l))*DM + d];
    float fu = gf*fwd + gb*bwd;

    float s1 = fu, s2 = fu*fu;
#pragma unroll
    for (int o = 16; o > 0; o >>= 1) {
        s1 += __shfl_xor_sync(0xffffffffu, s1, o);
        s2 += __shfl_xor_sync(0xffffffffu, s2, o);
    }
    __shared__ float r1[8], r2[8];
    if ((d & 31) == 0) { r1[d >> 5] = s1; r2[d >> 5] = s2; }
    __syncthreads();
    if (d < 32) {
        float v1 = (d < 8) ? r1[d] : 0.f;
        float v2 = (d < 8) ? r2[d] : 0.f;
#pragma unroll
        for (int o = 4; o > 0; o >>= 1) {
            v1 += __shfl_xor_sync(0xffffffffu, v1, o);
            v2 += __shfl_xor_sync(0xffffffffu, v2, o);
        }
        if (d == 0) { r1[0] = v1; r2[0] = v2; }
    }
    __syncthreads();
    float mu = r1[0] * (1.f/DM);
    float var = r2[0] * (1.f/DM) - mu*mu;
    float inv = rsqrtf(var + 1e-5f);
    out[(size_t)m*DM + d] = (fu - mu) * inv * lnw[d] + lnb[d];
}

// ---------------------------------------------------------------------------
extern "C" void kernel_launch(void* const* d_in, const int* in_sizes, int n_in,
                              void* d_out, int out_size) {
    const int*   ids  = (const int*)d_in[0];
    const float* mask = (const float*)d_in[1];
    const float* tok  = (const float*)d_in[2];
    const float* pos  = (const float*)d_in[3];
    const float* inw  = (const float*)d_in[4];
    const float* cw   = (const float*)d_in[5];
    const float* cb   = (const float*)d_in[6];
    const float* dtb  = (const float*)d_in[7];
    const float* alog = (const float*)d_in[8];
    const float* dpar = (const float*)d_in[9];
    const float* nw   = (const float*)d_in[10];
    const float* ow   = (const float*)d_in[11];
    const float* fw   = (const float*)d_in[12];
    const float* fb   = (const float*)d_in[13];
    const float* lnw  = (const float*)d_in[14];
    const float* lnb  = (const float*)d_in[15];

    float* scr = nullptr;
    cudaGetSymbolAddress((void**)&scr, g_scratch);
    float* pH    = scr + OFF_H;
    float* pZX   = scr + OFF_ZX;
    float* pNRM  = scr + OFF_NRM;
    float* pCOMB = scr + OFF_COMB;
    float* pGATE = scr + OFF_GATE;

    k_embed<<<M2, DM>>>(ids, mask, tok, pos);

    for (int layer = 0; layer < NLAYERS; layer++) {
        k_gemm<<<dim3((DIP + 63)/64, M2/128, 2), 256>>>(
            pH, inw + (size_t)layer*DIP*DM, pZX, M2, DIP, DM,
            (long)M2*DM, (long)NLAYERS*DIP*DM, (long)M2*DIP);
        k_conv<<<dim3(M2, 2), CD>>>(cw, cb, dtb, layer);
        k_scan1<<<512, 256>>>(alog, dpar, layer);
        k_scan2<<<512, 256>>>(alog, layer);
        k_scan3<<<512, 256>>>(alog, layer);
        k_gatedrms<<<dim3(M2, 2), DI>>>(nw, layer);
        k_gemm<<<dim3(DM/64, M2/128, 2), 256>>>(
            pNRM, ow + (size_t)layer*DM*DI, pH, M2, DM, DI,
            (long)M2*DI, (long)NLAYERS*DM*DI, (long)M2*DM);
    }

    k_comb<<<M2, 2*DM>>>();
    k_gemm<<<dim3(2*DM/64, M2/128, 1), 256>>>(pCOMB, fw, pGATE, M2, 2*DM, 2*DM, 0, 0, 0);
    k_final<<<M2, DM>>>(fb, lnw, lnb, (float*)d_out);
}

// round 5
// speedup vs baseline: 1.9016x; 1.2468x over previous
#include <cuda_runtime.h>
#include <cuda_bf16.h>
#include <math.h>
#include <cstdint>

#define BB 2
#define LSEQ 1024
#define DM 256
#define DI 512
#define DS 64
#define NH 8
#define HD 64
#define CD 640
#define DIP 1160
#define M2 (BB*LSEQ)
#define NLAYERS 2
#define NCHUNK 16
#define QCH 64

// ------------------------- fp32 scratch -------------------------------------
static constexpr size_t OFF_H    = 0;
static constexpr size_t OFF_ZX   = OFF_H    + (size_t)2*M2*DM;
static constexpr size_t OFF_CONV = OFF_ZX   + (size_t)2*M2*DIP;
static constexpr size_t OFF_DT   = OFF_CONV + (size_t)2*M2*CD;
static constexpr size_t OFF_Y    = OFF_DT   + (size_t)2*M2*NH;
static constexpr size_t OFF_GATE = OFF_Y    + (size_t)2*M2*DI;
static constexpr size_t OFF_HLOC = OFF_GATE + (size_t)M2*2*DM;
static constexpr size_t OFF_SDT  = OFF_HLOC + (size_t)32*NCHUNK*HD*DS;
static constexpr size_t OFF_CSUM = OFF_SDT  + (size_t)32*LSEQ;
static constexpr size_t SCRATCH_TOTAL = OFF_CSUM + (size_t)32*NCHUNK;

__device__ float g_scratch[SCRATCH_TOTAL];

// ------------------------- bf16 hi/lo scratch -------------------------------
static constexpr size_t B_ACTH  = 0;
static constexpr size_t B_ACTL  = B_ACTH  + (size_t)2*M2*DM;
static constexpr size_t B_NRMH  = B_ACTL  + (size_t)2*M2*DM;
static constexpr size_t B_NRML  = B_NRMH  + (size_t)2*M2*DI;
static constexpr size_t B_COMBH = B_NRML  + (size_t)2*M2*DI;
static constexpr size_t B_COMBL = B_COMBH + (size_t)M2*2*DM;
static constexpr size_t B_WINH  = B_COMBL + (size_t)M2*2*DM;
static constexpr size_t B_WINL  = B_WINH  + (size_t)2*NLAYERS*DIP*DM;
static constexpr size_t B_WOUTH = B_WINL  + (size_t)2*NLAYERS*DIP*DM;
static constexpr size_t B_WOUTL = B_WOUTH + (size_t)2*NLAYERS*DM*DI;
static constexpr size_t B_WFUSH = B_WOUTL + (size_t)2*NLAYERS*DM*DI;
static constexpr size_t B_WFUSL = B_WFUSH + (size_t)(2*DM)*(2*DM);
static constexpr size_t BF_TOTAL = B_WFUSL + (size_t)(2*DM)*(2*DM);

__device__ __align__(16) __nv_bfloat16 g_bf[BF_TOTAL];

typedef unsigned long long ull;

// ---- packed fp32x2 helpers (scan) ------------------------------------------
__device__ __forceinline__ ull pk2(float a, float b) {
    ull r;
    asm("mov.b64 %0, {%1, %2};" : "=l"(r) : "r"(__float_as_int(a)), "r"(__float_as_int(b)));
    return r;
}
__device__ __forceinline__ void upk2(ull v, float& a, float& b) {
    unsigned int x, y;
    asm("mov.b64 {%0, %1}, %2;" : "=r"(x), "=r"(y) : "l"(v));
    a = __int_as_float(x); b = __int_as_float(y);
}
__device__ __forceinline__ void fma2(ull& d, ull a, ull b) {
    asm("fma.rn.f32x2 %0, %1, %2, %0;" : "+l"(d) : "l"(a), "l"(b));
}
__device__ __forceinline__ ull mul2(ull a, ull b) {
    ull r; asm("mul.rn.f32x2 %0, %1, %2;" : "=l"(r) : "l"(a), "l"(b)); return r;
}

// ---- HMMA helpers -----------------------------------------------------------
__device__ __forceinline__ uint32_t smem_u32(const void* p) {
    uint32_t a;
    asm("{ .reg .u64 t; cvta.to.shared.u64 t, %1; cvt.u32.u64 %0, t; }" : "=r"(a) : "l"(p));
    return a;
}
__device__ __forceinline__ void ldsm_x4(uint32_t* r, uint32_t addr) {
    asm volatile("ldmatrix.sync.aligned.m8n8.x4.shared.b16 {%0,%1,%2,%3}, [%4];"
        : "=r"(r[0]), "=r"(r[1]), "=r"(r[2]), "=r"(r[3]) : "r"(addr));
}
__device__ __forceinline__ void mma16816(float* d, const uint32_t* a, const uint32_t* b) {
    asm volatile("mma.sync.aligned.m16n8k16.row.col.f32.bf16.bf16.f32 "
        "{%0,%1,%2,%3}, {%4,%5,%6,%7}, {%8,%9}, {%0,%1,%2,%3};"
        : "+f"(d[0]), "+f"(d[1]), "+f"(d[2]), "+f"(d[3])
        : "r"(a[0]), "r"(a[1]), "r"(a[2]), "r"(a[3]), "r"(b[0]), "r"(b[1]));
}

// ---------------- fp32 -> bf16 hi/lo conversion -----------------------------
__global__ void k_cvt(const float* __restrict__ x, size_t offH, size_t offL, int n) {
    int i = (blockIdx.x*blockDim.x + threadIdx.x)*4;
    if (i >= n) return;
    float4 v = *(const float4*)(x + i);
    float vv[4] = {v.x, v.y, v.z, v.w};
#pragma unroll
    for (int k = 0; k < 4; k++) {
        __nv_bfloat16 h = __float2bfloat16(vv[k]);
        g_bf[offH + i + k] = h;
        g_bf[offL + i + k] = __float2bfloat16(vv[k] - __bfloat162float(h));
    }
}

// ---------------- HMMA split-bf16 GEMM: C[M,N] = A[M,K] @ W[N,K]^T ----------
// Block 128x64 tile, 8 warps (4 m-groups x 2 n-groups), warp tile 32x32, Kc=32.
#define KC 32
#define SA 40   // smem row stride in halves (32 + 8 pad)

__global__ __launch_bounds__(256) void k_mma_gemm(
        size_t oAh, size_t oAl, size_t oWh, size_t oWl,
        float* __restrict__ C, int M, int N, int K,
        long sAz, long sWz, long sCz) {
    const __nv_bfloat16* Ah = g_bf + oAh + (long)blockIdx.z * sAz;
    const __nv_bfloat16* Al = g_bf + oAl + (long)blockIdx.z * sAz;
    const __nv_bfloat16* Wh = g_bf + oWh + (long)blockIdx.z * sWz;
    const __nv_bfloat16* Wl = g_bf + oWl + (long)blockIdx.z * sWz;
    C += (long)blockIdx.z * sCz;

    __shared__ __align__(16) __nv_bfloat16 sAh[128*SA];
    __shared__ __align__(16) __nv_bfloat16 sAl[128*SA];
    __shared__ __align__(16) __nv_bfloat16 sWh[64*SA];
    __shared__ __align__(16) __nv_bfloat16 sWl[64*SA];

    int tid = threadIdx.x;
    int warp = tid >> 5, lane = tid & 31;
    int wm = warp & 3, wn = warp >> 2;      // warp tile (wm*32 rows, wn*32 cols)
    int m0 = blockIdx.y * 128, n0 = blockIdx.x * 64;

    float acc[2][4][4];
#pragma unroll
    for (int i = 0; i < 2; i++)
#pragma unroll
        for (int j = 0; j < 4; j++)
#pragma unroll
            for (int k = 0; k < 4; k++) acc[i][j][k] = 0.f;

    // ldmatrix lane addresses (byte offsets within smem tiles)
    int a_r  = (lane & 15);
    int a_k  = (lane >> 4) << 3;
    int b_r  = ((lane >> 4) & 1) * 8 + (lane & 7);
    int b_k  = ((lane >> 3) & 1) * 8;

    uint32_t baseAh = smem_u32(sAh), baseAl = smem_u32(sAl);
    uint32_t baseWh = smem_u32(sWh), baseWl = smem_u32(sWl);

    int KT = K / KC;
    for (int c = 0; c < KT; c++) {
        int k0 = c * KC;
        // stage A: 128 rows x 32 halves = 512 16B chunks; 2 per thread
#pragma unroll
        for (int i = 0; i < 2; i++) {
            int id = tid + i*256;
            int r = id >> 2, c8 = (id & 3) * 8;
            *(uint4*)&sAh[r*SA + c8] = *(const uint4*)(Ah + (size_t)(m0 + r)*K + k0 + c8);
            *(uint4*)&sAl[r*SA + c8] = *(const uint4*)(Al + (size_t)(m0 + r)*K + k0 + c8);
        }
        // stage W: 64 rows x 32 halves = 256 chunks; 1 per thread
        {
            int r = tid >> 2, c8 = (tid & 3) * 8;
            uint4 vh = make_uint4(0u,0u,0u,0u), vl = make_uint4(0u,0u,0u,0u);
            if (n0 + r < N) {
                vh = *(const uint4*)(Wh + (size_t)(n0 + r)*K + k0 + c8);
                vl = *(const uint4*)(Wl + (size_t)(n0 + r)*K + k0 + c8);
            }
            *(uint4*)&sWh[r*SA + c8] = vh;
            *(uint4*)&sWl[r*SA + c8] = vl;
        }
        __syncthreads();

#pragma unroll
        for (int km = 0; km < 2; km++) {
            uint32_t ah[2][4], al[2][4], bh[4][2], bl[4][2];
#pragma unroll
            for (int mi = 0; mi < 2; mi++) {
                int off = ((wm*32 + mi*16 + a_r)*SA + km*16 + a_k) * 2;
                ldsm_x4(ah[mi], baseAh + off);
                ldsm_x4(al[mi], baseAl + off);
            }
#pragma unroll
            for (int np = 0; np < 2; np++) {   // ni pair (2*np, 2*np+1)
                int row = wn*32 + (np*2 + ((lane >> 4) & 1))*8 + (lane & 7);
                int off = (row*SA + km*16 + b_k) * 2;
                uint32_t t4[4];
                ldsm_x4(t4, baseWh + off);
                bh[np*2][0] = t4[0]; bh[np*2][1] = t4[1];
                bh[np*2+1][0] = t4[2]; bh[np*2+1][1] = t4[3];
                ldsm_x4(t4, baseWl + off);
                bl[np*2][0] = t4[0]; bl[np*2][1] = t4[1];
                bl[np*2+1][0] = t4[2]; bl[np*2+1][1] = t4[3];
            }
#pragma unroll
            for (int mi = 0; mi < 2; mi++)
#pragma unroll
                for (int ni = 0; ni < 4; ni++) {
                    mma16816(acc[mi][ni], ah[mi], bh[ni]);
                    mma16816(acc[mi][ni], ah[mi], bl[ni]);
                    mma16816(acc[mi][ni], al[mi], bh[ni]);
                }
        }
        __syncthreads();
    }

    // epilogue: direct stores (float2 per d-pair)
#pragma unroll
    for (int mi = 0; mi < 2; mi++) {
#pragma unroll
        for (int ni = 0; ni < 4; ni++) {
            int m = m0 + wm*32 + mi*16 + (lane >> 2);
            int n = n0 + wn*32 + ni*8 + (lane & 3)*2;
            if (n < N) {
                *(float2*)(C + (size_t)m*N + n) = make_float2(acc[mi][ni][0], acc[mi][ni][1]);
                *(float2*)(C + (size_t)(m+8)*N + n) = make_float2(acc[mi][ni][2], acc[mi][ni][3]);
            }
        }
    }
}

// ---------------- embedding -------------------------------------------------
__global__ void k_embed(const int* __restrict__ ids, const float* __restrict__ mask,
                        const float* __restrict__ tok, const float* __restrict__ pos) {
    int bl = blockIdx.x;
    int d  = threadIdx.x;
    int b = bl / LSEQ, l = bl % LSEQ;
    int id = ids[bl];
    float v = (tok[(size_t)id*DM + d] + pos[(size_t)l*DM + d]) * mask[bl];
    g_scratch[OFF_H + (size_t)bl*DM + d] = v;
    g_scratch[OFF_H + (size_t)M2*DM + ((size_t)b*LSEQ + (LSEQ-1-l))*DM + d] = v;
}

// ---------------- depthwise causal conv(4) + SiLU + dt softplus -------------
__global__ void k_conv(const float* __restrict__ cw, const float* __restrict__ cbias,
                       const float* __restrict__ dtb, int layer) {
    int dir = blockIdx.y;
    int bl = blockIdx.x;
    int b = bl / LSEQ, l = bl % LSEQ;
    int c = threadIdx.x;
    int li = dir*NLAYERS + layer;
    const float* zx = g_scratch + OFF_ZX + (size_t)dir*M2*DIP;
    float4 w = *(const float4*)(cw + ((size_t)li*CD + c)*4);
    float wk[4] = {w.x, w.y, w.z, w.w};
    float acc = 0.f;
#pragma unroll
    for (int k = 0; k < 4; k++) {
        int ls = l - 3 + k;
        if (ls >= 0)
            acc += zx[((size_t)b*LSEQ + ls)*DIP + DI + c] * wk[k];
    }
    acc += cbias[(size_t)li*CD + c];
    float s = acc / (1.f + __expf(-acc));
    g_scratch[OFF_CONV + (size_t)dir*M2*CD + (size_t)bl*CD + c] = s;
    if (c < NH) {
        float raw = zx[(size_t)bl*DIP + DI + CD + c] + dtb[li*NH + c];
        float sp = (raw > 20.f) ? raw : log1pf(expf(raw));
        g_scratch[OFF_DT + (size_t)dir*M2*NH + (size_t)bl*NH + c] = sp;
    }
}

// ---------------- scan pass 1 ------------------------------------------------
__global__ __launch_bounds__(256) void k_scan1(const float* __restrict__ A_log,
                                               const float* __restrict__ Dp, int layer) {
    int idx = blockIdx.x;
    int chunk = idx & 15; idx >>= 4;
    int hh = idx & 7; idx >>= 3;
    int b = idx & 1; int dir = idx >> 1;
    int hg = (dir*2 + b)*8 + hh;
    int tid = threadIdx.x;
    int ql = tid & 3, p = tid >> 2;
    int li = dir*NLAYERS + layer;
    float Aa = -expf(A_log[li*NH + hh]);
    float Dv = Dp[li*NH + hh];
    const float* conv = g_scratch + OFF_CONV + (size_t)dir*M2*CD + (size_t)b*LSEQ*CD;
    const float* dt   = g_scratch + OFF_DT   + (size_t)dir*M2*NH + (size_t)b*LSEQ*NH;
    float* y          = g_scratch + OFF_Y    + (size_t)dir*M2*DI + (size_t)b*LSEQ*DI;
    float* sdt_g      = g_scratch + OFF_SDT  + (size_t)hg*LSEQ;

    __shared__ float sB[16][64];
    __shared__ float sC[16][64];
    __shared__ float sx[16][64];
    __shared__ float sdt[16];

    ull h2[8];
#pragma unroll
    for (int k = 0; k < 8; k++) h2[k] = 0ULL;
    float runsum = 0.f;

    int js = tid >> 4, c4 = (tid & 15) * 4;

    for (int t = 0; t < 4; t++) {
        int s0 = chunk*QCH + t*16;
        {
            const float* cr = conv + (size_t)(s0 + js)*CD;
            *(float4*)&sB[js][c4] = *(const float4*)(cr + DI + c4);
            *(float4*)&sC[js][c4] = *(const float4*)(cr + DI + DS + c4);
            *(float4*)&sx[js][c4] = *(const float4*)(cr + hh*HD + c4);
            if (tid < 16) sdt[tid] = dt[(size_t)(s0 + tid)*NH + hh];
        }
        __syncthreads();
        if (tid == 0) {
            float rs = runsum;
#pragma unroll
            for (int j = 0; j < 16; j++) { rs += sdt[j]; sdt_g[s0 + j] = rs; }
            runsum = rs;
        }
#pragma unroll 4
        for (int j = 0; j < 16; j++) {
            float dtv = sdt[j];
            float dA = __expf(dtv * Aa);
            float xv = sx[j][p];
            float sc = dtv * xv;
            ull dA2 = pk2(dA, dA), sc2 = pk2(sc, sc);
            const ulonglong2* pB = (const ulonglong2*)&sB[j][ql*16];
            const ulonglong2* pC = (const ulonglong2*)&sC[j][ql*16];
            ulonglong2 b01 = pB[0], b23 = pB[1], b45 = pB[2], b67 = pB[3];
            ulonglong2 c01 = pC[0], c23 = pC[1], c45 = pC[2], c67 = pC[3];
            ull Bv[8] = {b01.x,b01.y,b23.x,b23.y,b45.x,b45.y,b67.x,b67.y};
            ull Cv[8] = {c01.x,c01.y,c23.x,c23.y,c45.x,c45.y,c67.x,c67.y};
            ull acc2 = 0ULL;
#pragma unroll
            for (int k = 0; k < 8; k++) {
                ull tmp = mul2(sc2, Bv[k]);
                fma2(h2[k], dA2, tmp);
                fma2(acc2, h2[k], Cv[k]);
            }
            float alo, ahi; upk2(acc2, alo, ahi);
            float acc = alo + ahi;
            acc += __shfl_xor_sync(0xffffffffu, acc, 1);
            acc += __shfl_xor_sync(0xffffffffu, acc, 2);
            if (ql == 0) y[(size_t)(s0 + j)*DI + hh*HD + p] = acc + Dv*xv;
        }
        __syncthreads();
    }
    if (tid == 0) g_scratch[OFF_CSUM + hg*NCHUNK + chunk] = runsum;

    float* hl = g_scratch + OFF_HLOC + ((size_t)hg*NCHUNK + chunk)*(HD*DS)
              + (size_t)p*DS + ql*16;
    ((ulonglong2*)hl)[0] = make_ulonglong2(h2[0], h2[1]);
    ((ulonglong2*)hl)[1] = make_ulonglong2(h2[2], h2[3]);
    ((ulonglong2*)hl)[2] = make_ulonglong2(h2[4], h2[5]);
    ((ulonglong2*)hl)[3] = make_ulonglong2(h2[6], h2[7]);
}

// ---------------- scan pass 2 ------------------------------------------------
__global__ __launch_bounds__(256) void k_scan2(const float* __restrict__ A_log, int layer) {
    int hg = blockIdx.x >> 4;
    int e  = (blockIdx.x & 15)*256 + threadIdx.x;
    int dir = hg >> 4, hh = hg & 7;
    int li = dir*NLAYERS + layer;
    float Aa = -expf(A_log[li*NH + hh]);
    const float* csum = g_scratch + OFF_CSUM + hg*NCHUNK;
    float* hl = g_scratch + OFF_HLOC + (size_t)hg*NCHUNK*(HD*DS) + e;
    float tmp[NCHUNK];
#pragma unroll
    for (int c = 0; c < NCHUNK; c++) tmp[c] = hl[(size_t)c*(HD*DS)];
    float carry = 0.f;
#pragma unroll
    for (int c = 0; c < NCHUNK; c++) {
        hl[(size_t)c*(HD*DS)] = carry;
        carry = carry * __expf(Aa * csum[c]) + tmp[c];
    }
}

// ---------------- scan pass 3 ------------------------------------------------
__global__ __launch_bounds__(256) void k_scan3(const float* __restrict__ A_log, int layer) {
    int idx = blockIdx.x;
    int chunk = idx & 15; idx >>= 4;
    if (chunk == 0) return;
    int hh = idx & 7; idx >>= 3;
    int b = idx & 1; int dir = idx >> 1;
    int hg = (dir*2 + b)*8 + hh;
    int tid = threadIdx.x;
    int ql = tid & 3, p = tid >> 2;
    int li = dir*NLAYERS + layer;
    float Aa = -expf(A_log[li*NH + hh]);
    const float* conv = g_scratch + OFF_CONV + (size_t)dir*M2*CD + (size_t)b*LSEQ*CD;
    float* y          = g_scratch + OFF_Y    + (size_t)dir*M2*DI + (size_t)b*LSEQ*DI;
    const float* sdt_g= g_scratch + OFF_SDT  + (size_t)hg*LSEQ;
    const float* hl   = g_scratch + OFF_HLOC + ((size_t)hg*NCHUNK + chunk)*(HD*DS)
                      + (size_t)p*DS + ql*16;
    ulonglong2 h01 = ((const ulonglong2*)hl)[0];
    ulonglong2 h23 = ((const ulonglong2*)hl)[1];
    ulonglong2 h45 = ((const ulonglong2*)hl)[2];
    ulonglong2 h67 = ((const ulonglong2*)hl)[3];
    ull Hv[8] = {h01.x,h01.y,h23.x,h23.y,h45.x,h45.y,h67.x,h67.y};

    __shared__ float sC[16][64];
    __shared__ float sdt[16];
    int js = tid >> 4, c4 = (tid & 15) * 4;

    for (int t = 0; t < 4; t++) {
        int s0 = chunk*QCH + t*16;
        {
            const float* cr = conv + (size_t)(s0 + js)*CD;
            *(float4*)&sC[js][c4] = *(const float4*)(cr + DI + DS + c4);
            if (tid < 16) sdt[tid] = sdt_g[s0 + tid];
        }
        __syncthreads();
#pragma unroll 4
        for (int j = 0; j < 16; j++) {
            const ulonglong2* pC = (const ulonglong2*)&sC[j][ql*16];
            ulonglong2 c01 = pC[0], c23 = pC[1], c45 = pC[2], c67 = pC[3];
            ull Cv[8] = {c01.x,c01.y,c23.x,c23.y,c45.x,c45.y,c67.x,c67.y};
            ull acc2 = 0ULL;
#pragma unroll
            for (int k = 0; k < 8; k++) fma2(acc2, Hv[k], Cv[k]);
            float alo, ahi; upk2(acc2, alo, ahi);
            float acc = alo + ahi;
            acc += __shfl_xor_sync(0xffffffffu, acc, 1);
            acc += __shfl_xor_sync(0xffffffffu, acc, 2);
            if (ql == 0) {
                float cum = __expf(Aa * sdt[j]);
                y[(size_t)(s0 + j)*DI + hh*HD + p] += cum * acc;
            }
        }
        __syncthreads();
    }
}

// ---------------- gated RMSNorm (writes bf16 hi/lo for out_proj) -------------
__global__ __launch_bounds__(512) void k_gatedrms(const float* __restrict__ nw, int layer) {
    int dir = blockIdx.y;
    int m = blockIdx.x;
    int i = threadIdx.x;
    int li = dir*NLAYERS + layer;
    float yv = g_scratch[OFF_Y + (size_t)dir*M2*DI + (size_t)m*DI + i];
    float zv = g_scratch[OFF_ZX + (size_t)dir*M2*DIP + (size_t)m*DIP + i];
    float g = yv * (zv / (1.f + __expf(-zv)));
    float ss = g * g;
#pragma unroll
    for (int o = 16; o > 0; o >>= 1) ss += __shfl_xor_sync(0xffffffffu, ss, o);
    __shared__ float red[16];
    if ((i & 31) == 0) red[i >> 5] = ss;
    __syncthreads();
    if (i < 32) {
        float v = (i < 16) ? red[i] : 0.f;
#pragma unroll
        for (int o = 8; o > 0; o >>= 1) v += __shfl_xor_sync(0xffffffffu, v, o);
        if (i == 0) red[0] = v;
    }
    __syncthreads();
    float inv = rsqrtf(red[0] * (1.f/DI) + 1e-5f);
    float o = g * inv * nw[(size_t)li*DI + i];
    size_t oi = (size_t)dir*M2*DI + (size_t)m*DI + i;
    __nv_bfloat16 hb = __float2bfloat16(o);
    g_bf[B_NRMH + oi] = hb;
    g_bf[B_NRML + oi] = __float2bfloat16(o - __bfloat162float(hb));
}

// ---------------- combine fwd + flipped bwd (bf16 hi/lo) ---------------------
__global__ void k_comb() {
    int m = blockIdx.x;
    int i = threadIdx.x;
    int b = m / LSEQ, l = m % LSEQ;
    float v;
    if (i < DM) v = g_scratch[OFF_H + (size_t)m*DM + i];
    else        v = g_scratch[OFF_H + (size_t)M2*DM + ((size_t)b*LSEQ + (LSEQ-1-l))*DM + (i-DM)];
    size_t oi = (size_t)m*2*DM + i;
    __nv_bfloat16 hb = __float2bfloat16(v);
    g_bf[B_COMBH + oi] = hb;
    g_bf[B_COMBL + oi] = __float2bfloat16(v - __bfloat162float(hb));
}

// ---------------- gate sigmoid + fuse + LayerNorm ---------------------------
__global__ __launch_bounds__(256) void k_final(const float* __restrict__ fb,
                                               const float* __restrict__ lnw,
                                               const float* __restrict__ lnb,
                                               float* __restrict__ out) {
    int m = blockIdx.x;
    int d = threadIdx.x;
    int b = m / LSEQ, l = m % LSEQ;
    float gl0 = g_scratch[OFF_GATE + (size_t)m*2*DM + d] + fb[d];
    float gl1 = g_scratch[OFF_GATE + (size_t)m*2*DM + DM + d] + fb[DM + d];
    float gf = 1.f / (1.f + __expf(-gl0));
    float gb = 1.f / (1.f + __expf(-gl1));
    float fwd = g_scratch[OFF_H + (size_t)m*DM + d];
    float bwd = g_scratch[OFF_H + (size_t)M2*DM + ((size_t)b*LSEQ + (LSEQ-1-l))*DM + d];
    float fu = gf*fwd + gb*bwd;

    float s1 = fu, s2 = fu*fu;
#pragma unroll
    for (int o = 16; o > 0; o >>= 1) {
        s1 += __shfl_xor_sync(0xffffffffu, s1, o);
        s2 += __shfl_xor_sync(0xffffffffu, s2, o);
    }
    __shared__ float r1[8], r2[8];
    if ((d & 31) == 0) { r1[d >> 5] = s1; r2[d >> 5] = s2; }
    __syncthreads();
    if (d < 32) {
        float v1 = (d < 8) ? r1[d] : 0.f;
        float v2 = (d < 8) ? r2[d] : 0.f;
#pragma unroll
        for (int o = 4; o > 0; o >>= 1) {
            v1 += __shfl_xor_sync(0xffffffffu, v1, o);
            v2 += __shfl_xor_sync(0xffffffffu, v2, o);
        }
        if (d == 0) { r1[0] = v1; r2[0] = v2; }
    }
    __syncthreads();
    float mu = r1[0] * (1.f/DM);
    float var = r2[0] * (1.f/DM) - mu*mu;
    float inv = rsqrtf(var + 1e-5f);
    out[(size_t)m*DM + d] = (fu - mu) * inv * lnw[d] + lnb[d];
}

// ---------------------------------------------------------------------------
extern "C" void kernel_launch(void* const* d_in, const int* in_sizes, int n_in,
                              void* d_out, int out_size) {
    const int*   ids  = (const int*)d_in[0];
    const float* mask = (const float*)d_in[1];
    const float* tok  = (const float*)d_in[2];
    const float* pos  = (const float*)d_in[3];
    const float* inw  = (const float*)d_in[4];
    const float* cw   = (const float*)d_in[5];
    const float* cb   = (const float*)d_in[6];
    const float* dtb  = (const float*)d_in[7];
    const float* alog = (const float*)d_in[8];
    const float* dpar = (const float*)d_in[9];
    const float* nw   = (const float*)d_in[10];
    const float* ow   = (const float*)d_in[11];
    const float* fw   = (const float*)d_in[12];
    const float* fb   = (const float*)d_in[13];
    const float* lnw  = (const float*)d_in[14];
    const float* lnb  = (const float*)d_in[15];

    float* scr = nullptr;
    cudaGetSymbolAddress((void**)&scr, g_scratch);
    float* pH    = scr + OFF_H;
    float* pZX   = scr + OFF_ZX;
    float* pGATE = scr + OFF_GATE;

    // convert weights to bf16 hi/lo
    {
        int nW = 2*NLAYERS*DIP*DM;
        k_cvt<<<(nW/4 + 255)/256, 256>>>(inw, B_WINH, B_WINL, nW);
        int nO = 2*NLAYERS*DM*DI;
        k_cvt<<<(nO/4 + 255)/256, 256>>>(ow, B_WOUTH, B_WOUTL, nO);
        int nF = (2*DM)*(2*DM);
        k_cvt<<<(nF/4 + 255)/256, 256>>>(fw, B_WFUSH, B_WFUSL, nF);
    }

    k_embed<<<M2, DM>>>(ids, mask, tok, pos);
    k_cvt<<<(2*M2*DM/4 + 255)/256, 256>>>(pH, B_ACTH, B_ACTL, 2*M2*DM);

    for (int layer = 0; layer < NLAYERS; layer++) {
        // in_proj: [M2, DIP] = act @ inw^T, both dirs
        k_mma_gemm<<<dim3((DIP + 63)/64, M2/128, 2), 256>>>(
            B_ACTH, B_ACTL,
            B_WINH + (size_t)layer*DIP*DM, B_WINL + (size_t)layer*DIP*DM,
            pZX, M2, DIP, DM,
            (long)M2*DM, (long)NLAYERS*DIP*DM, (long)M2*DIP);
        k_conv<<<dim3(M2, 2), CD>>>(cw, cb, dtb, layer);
        k_scan1<<<512, 256>>>(alog, dpar, layer);
        k_scan2<<<512, 256>>>(alog, layer);
        k_scan3<<<512, 256>>>(alog, layer);
        k_gatedrms<<<dim3(M2, 2), DI>>>(nw, layer);
        // out_proj: [M2, DM] = nrm @ ow^T, both dirs
        k_mma_gemm<<<dim3(DM/64, M2/128, 2), 256>>>(
            B_NRMH, B_NRML,
            B_WOUTH + (size_t)layer*DM*DI, B_WOUTL + (size_t)layer*DM*DI,
            pH, M2, DM, DI,
            (long)M2*DI, (long)NLAYERS*DM*DI, (long)M2*DM);
        if (layer + 1 < NLAYERS)
            k_cvt<<<(2*M2*DM/4 + 255)/256, 256>>>(pH, B_ACTH, B_ACTL, 2*M2*DM);
    }

    k_comb<<<M2, 2*DM>>>();
    k_mma_gemm<<<dim3(2*DM/64, M2/128, 1), 256>>>(
        B_COMBH, B_COMBL, B_WFUSH, B_WFUSL,
        pGATE, M2, 2*DM, 2*DM, 0, 0, 0);
    k_final<<<M2, DM>>>(fb, lnw, lnb, (float*)d_out);
}